// round 12
// baseline (speedup 1.0000x reference)
#include <cuda_runtime.h>
#include <cuda_fp16.h>
#include <cstdint>

#define NN 10000
#define EE 640000
#define D  128
#define M2 (2*NN)
#define GEMM_BLOCKS ((M2 + 127) / 128)      // 157
#define EPT 16                               // edges per thread in fused fill

// ---------------- scratch (static __device__, no allocation) ----------------
__device__ int   g_is64;
__device__ int   g_deg[NN];
__device__ int   g_rowptr[NN + 1];
__device__ float g_dinv[NN];
__device__ int   g_rank[EE];
__device__ int   g_src[EE];
__device__ __align__(16) float  g_H[(size_t)M2 * D];     // node features (both seqs)
__device__ __align__(16) __half g_Yh[(size_t)NN * 256];  // interleaved node row: 256 halves (seq1|seq2)
__device__ float g_colsum[D];
__device__ float g_wc[D];

__device__ __forceinline__ unsigned h2_bits(__half2 h) {
    union { __half2 h; unsigned u; } cv; cv.h = h; return cv.u;
}
__device__ __forceinline__ uint32_t smem_u32(const void* p) {
    uint32_t a;
    asm("{ .reg .u64 t; cvta.to.shared.u64 t, %1; cvt.u32.u64 %0, t; }"
        : "=r"(a) : "l"(p));
    return a;
}

// ---------------- init + dtype probe (int64 => odd int32 words all zero) ----
__global__ void init_kernel(const int* __restrict__ ei32) {
    if (blockIdx.x == 0 && threadIdx.x < 32) {
        int odd = ei32[2 * threadIdx.x + 1];
        unsigned m = __ballot_sync(0xffffffffu, odd != 0);
        if (threadIdx.x == 0) g_is64 = (m == 0);
    }
    int i = blockIdx.x * blockDim.x + threadIdx.x;
    if (i < NN) g_deg[i] = 0;
    if (i < D)  g_colsum[i] = 0.f;
}

// ---------------- histogram + per-edge rank: 4 edges/thread ----------------
__global__ void hist_kernel(const void* __restrict__ ei) {
    int e = (blockIdx.x * blockDim.x + threadIdx.x) * 4;
    if (e >= EE) return;
    int c0, c1, c2, c3;
    if (g_is64) {
        const ulonglong2* p = (const ulonglong2*)((const long long*)ei + EE + e);
        ulonglong2 v0 = p[0], v1 = p[1];
        c0 = (int)v0.x; c1 = (int)v0.y; c2 = (int)v1.x; c3 = (int)v1.y;
    } else {
        int4 v = *(const int4*)((const int*)ei + EE + e);
        c0 = v.x; c1 = v.y; c2 = v.z; c3 = v.w;
    }
    int4 rk;
    rk.x = ((unsigned)c0 < NN) ? atomicAdd(&g_deg[c0], 1) : -1;
    rk.y = ((unsigned)c1 < NN) ? atomicAdd(&g_deg[c1], 1) : -1;
    rk.z = ((unsigned)c2 < NN) ? atomicAdd(&g_deg[c2], 1) : -1;
    rk.w = ((unsigned)c3 < NN) ? atomicAdd(&g_deg[c3], 1) : -1;
    *(int4*)(g_rank + e) = rk;
}

// single block, 1024 threads, 10 elems/thread
__global__ void scan_kernel() {
    const int PER = 10;
    int tid  = threadIdx.x;
    int lane = tid & 31, w = tid >> 5;
    int base = tid * PER;
    int v[PER];
    int s = 0;
#pragma unroll
    for (int k = 0; k < PER; k++) {
        int i = base + k;
        int d = (i < NN) ? g_deg[i] : 0;
        v[k] = d; s += d;
        if (i < NN) g_dinv[i] = rsqrtf((float)(d + 1));
    }
    int ws = s;
#pragma unroll
    for (int o = 1; o < 32; o <<= 1) {
        int t = __shfl_up_sync(0xffffffffu, ws, o);
        if (lane >= o) ws += t;
    }
    __shared__ int wsum[32];
    if (lane == 31) wsum[w] = ws;
    __syncthreads();
    if (w == 0) {
        int x = wsum[lane];
#pragma unroll
        for (int o = 1; o < 32; o <<= 1) {
            int t = __shfl_up_sync(0xffffffffu, x, o);
            if (lane >= o) x += t;
        }
        wsum[lane] = x;
    }
    __syncthreads();
    int run = ws - s + (w ? wsum[w - 1] : 0);
#pragma unroll
    for (int k = 0; k < PER; k++) {
        int i = base + k;
        if (i <= NN) g_rowptr[i] = run;
        run += v[k];
    }
}

// ---------------- fill prologue: EPT edges/thread, fire-and-forget ----------
__device__ __forceinline__ void fill4(const void* __restrict__ ei, int e) {
    if (e >= EE) return;
    int r0, r1, r2, r3, c0, c1, c2, c3;
    if (g_is64) {
        const ulonglong2* pr = (const ulonglong2*)((const long long*)ei + e);
        const ulonglong2* pc = (const ulonglong2*)((const long long*)ei + EE + e);
        ulonglong2 a0 = pr[0], a1 = pr[1], b0 = pc[0], b1 = pc[1];
        r0 = (int)a0.x; r1 = (int)a0.y; r2 = (int)a1.x; r3 = (int)a1.y;
        c0 = (int)b0.x; c1 = (int)b0.y; c2 = (int)b1.x; c3 = (int)b1.y;
    } else {
        int4 a = *(const int4*)((const int*)ei + e);
        int4 b = *(const int4*)((const int*)ei + EE + e);
        r0 = a.x; r1 = a.y; r2 = a.z; r3 = a.w;
        c0 = b.x; c1 = b.y; c2 = b.z; c3 = b.w;
    }
    int4 rk = *(const int4*)(g_rank + e);
    if (rk.x >= 0 && (unsigned)r0 < NN) g_src[g_rowptr[c0] + rk.x] = r0;
    if (rk.y >= 0 && (unsigned)r1 < NN) g_src[g_rowptr[c1] + rk.y] = r1;
    if (rk.z >= 0 && (unsigned)r2 < NN) g_src[g_rowptr[c2] + rk.z] = r2;
    if (rk.w >= 0 && (unsigned)r3 < NN) g_src[g_rowptr[c3] + rk.w] = r3;
}

// ---------------- split-fp16 HMMA GEMM body ---------------------------------
#define WSTR 136

__device__ __forceinline__ void gemm_body(__half* Wh, __half* Wl,
                                          const float* __restrict__ W,
                                          const float* __restrict__ base0,
                                          const float* __restrict__ base1,
                                          int bm) {
    int tid = threadIdx.x, wid = tid >> 5, lane = tid & 31;

    int grpID = lane >> 2, tig = lane & 3;
    int m0 = bm + wid * 16 + grpID;
    int m1 = m0 + 8;
    int m0c = (m0 < M2) ? m0 : M2 - 1;
    int m1c = (m1 < M2) ? m1 : M2 - 1;
    const float* ap0 = (m0c < NN) ? (base0 + (size_t)m0c * D)
                                  : (base1 + (size_t)(m0c - NN) * D);
    const float* ap1 = (m1c < NN) ? (base0 + (size_t)m1c * D)
                                  : (base1 + (size_t)(m1c - NN) * D);

    float c[16][4];
#pragma unroll
    for (int t = 0; t < 16; t++)
#pragma unroll
        for (int j = 0; j < 4; j++) c[t][j] = 0.f;

    int krow = lane & 15;
    int ngrp = (lane >> 4) * 8;

    for (int phase = 0; phase < 2; phase++) {
        for (int idx = tid; idx < 64 * 32; idx += 256) {
            int row = idx >> 5, c4 = (idx & 31) * 4;
            float4 v = *(const float4*)(W + (size_t)(phase * 64 + row) * D + c4);
            __half hx = __float2half_rn(v.x), hy = __float2half_rn(v.y);
            __half hz = __float2half_rn(v.z), hw = __float2half_rn(v.w);
            uint2 hi, lo;
            hi.x = h2_bits(__halves2half2(hx, hy));
            hi.y = h2_bits(__halves2half2(hz, hw));
            lo.x = h2_bits(__floats2half2_rn(v.x - __half2float(hx),
                                             v.y - __half2float(hy)));
            lo.y = h2_bits(__floats2half2_rn(v.z - __half2float(hz),
                                             v.w - __half2float(hw)));
            *(uint2*)(Wh + row * WSTR + c4) = hi;
            *(uint2*)(Wl + row * WSTR + c4) = lo;
        }
        __syncthreads();

#pragma unroll
        for (int kt = 0; kt < 4; kt++) {
            int kc = phase * 64 + kt * 16 + tig * 2;
            uint32_t ah[4], al[4];
#pragma unroll
            for (int q = 0; q < 4; q++) {
                const float* ap = (q & 1) ? ap1 : ap0;
                float2 v = *(const float2*)(ap + kc + (q >> 1) * 8);
                __half hx = __float2half_rn(v.x), hy = __float2half_rn(v.y);
                ah[q] = h2_bits(__halves2half2(hx, hy));
                al[q] = h2_bits(__floats2half2_rn(v.x - __half2float(hx),
                                                  v.y - __half2float(hy)));
            }

            uint32_t rowoff = (uint32_t)(kt * 16 + krow) * WSTR * 2 + ngrp * 2;
            uint32_t bh_addr = smem_u32(Wh) + rowoff;
            uint32_t bl_addr = smem_u32(Wl) + rowoff;
#pragma unroll
            for (int nt = 0; nt < 8; nt++) {
                uint32_t bh0, bh1, bh2, bh3, bl0, bl1, bl2, bl3;
                asm volatile(
                    "ldmatrix.sync.aligned.m8n8.x4.trans.shared.b16 {%0,%1,%2,%3}, [%4];"
                    : "=r"(bh0), "=r"(bh1), "=r"(bh2), "=r"(bh3)
                    : "r"(bh_addr + nt * 32));
                asm volatile(
                    "ldmatrix.sync.aligned.m8n8.x4.trans.shared.b16 {%0,%1,%2,%3}, [%4];"
                    : "=r"(bl0), "=r"(bl1), "=r"(bl2), "=r"(bl3)
                    : "r"(bl_addr + nt * 32));
#define MMA(CT, B0, B1, AH0, AH1, AH2, AH3)                                   \
    asm volatile(                                                             \
        "mma.sync.aligned.m16n8k16.row.col.f32.f16.f16.f32 "                  \
        "{%0,%1,%2,%3}, {%4,%5,%6,%7}, {%8,%9}, {%0,%1,%2,%3};"               \
        : "+f"(c[CT][0]), "+f"(c[CT][1]), "+f"(c[CT][2]), "+f"(c[CT][3])      \
        : "r"(AH0), "r"(AH1), "r"(AH2), "r"(AH3), "r"(B0), "r"(B1))
                MMA(nt * 2,     bh0, bh1, ah[0], ah[1], ah[2], ah[3]);
                MMA(nt * 2,     bh0, bh1, al[0], al[1], al[2], al[3]);
                MMA(nt * 2,     bl0, bl1, ah[0], ah[1], ah[2], ah[3]);
                MMA(nt * 2 + 1, bh2, bh3, ah[0], ah[1], ah[2], ah[3]);
                MMA(nt * 2 + 1, bh2, bh3, al[0], al[1], al[2], al[3]);
                MMA(nt * 2 + 1, bl2, bl3, ah[0], ah[1], ah[2], ah[3]);
#undef MMA
            }
        }
        __syncthreads();
    }

    // epilogue: scale by dinv, store fp16 into interleaved Y (node row = 512B)
    float dv0 = (m0 < M2) ? g_dinv[(m0 < NN) ? m0 : m0 - NN] : 0.f;
    float dv1 = (m1 < M2) ? g_dinv[(m1 < NN) ? m1 : m1 - NN] : 0.f;
    size_t y0 = (m0 < NN) ? ((size_t)m0 * 256) : ((size_t)(m0 - NN) * 256 + 128);
    size_t y1 = (m1 < NN) ? ((size_t)m1 * 256) : ((size_t)(m1 - NN) * 256 + 128);
#pragma unroll
    for (int t = 0; t < 16; t++) {
        int col = t * 8 + tig * 2;
        if (m0 < M2)
            *(unsigned*)(g_Yh + y0 + col) =
                h2_bits(__floats2half2_rn(dv0 * c[t][0], dv0 * c[t][1]));
        if (m1 < M2)
            *(unsigned*)(g_Yh + y1 + col) =
                h2_bits(__floats2half2_rn(dv1 * c[t][2], dv1 * c[t][3]));
    }
}

// standalone GEMM (layers 2,3)
__global__ __launch_bounds__(256) void gemm_mma_kernel(const float* __restrict__ W) {
    __shared__ __half Wh[64 * WSTR];
    __shared__ __half Wl[64 * WSTR];
    gemm_body(Wh, Wl, W, g_H, g_H + (size_t)NN * D, blockIdx.x * 128);
}

// fused layer-1: fill prologue (EPT edges/thread, async stores) + GEMM tile
__global__ __launch_bounds__(256) void gemm_fill_kernel(const float* __restrict__ W,
                                                        const float* __restrict__ seq1,
                                                        const float* __restrict__ seq2,
                                                        const void* __restrict__ ei) {
    __shared__ __half Wh[64 * WSTR];
    __shared__ __half Wl[64 * WSTR];
    int e0 = (blockIdx.x * 256 + threadIdx.x) * EPT;
#pragma unroll
    for (int j = 0; j < EPT / 4; j++) fill4(ei, e0 + j * 4);
    gemm_body(Wh, Wl, W, seq1, seq2, blockIdx.x * 128);
}

// ------- aggregation: warp/node, 16B per lane per edge (both seqs fused) ----
__global__ __launch_bounds__(256) void agg_kernel(const float* __restrict__ bias,
                                                  const float* __restrict__ aptr) {
    int c    = (blockIdx.x * blockDim.x + threadIdx.x) >> 5;
    int lane = threadIdx.x & 31;
    if (c >= NN) return;

    const uint4* Yq = (const uint4*)g_Yh;   // 32 uint4 per node row (512B)
    float a[8];
    {
        uint4 p = Yq[(size_t)c * 32 + lane];     // self loop
        __half2* h = (__half2*)&p;
#pragma unroll
        for (int i = 0; i < 4; i++) {
            float2 f = __half22float2(h[i]);
            a[2 * i] = f.x; a[2 * i + 1] = f.y;
        }
    }

    int e = g_rowptr[c], e1 = g_rowptr[c + 1];
    for (; e + 4 <= e1; e += 4) {
        int i0 = g_src[e + 0], i1 = g_src[e + 1];
        int i2 = g_src[e + 2], i3 = g_src[e + 3];
        uint4 p0 = Yq[(size_t)i0 * 32 + lane];
        uint4 p1 = Yq[(size_t)i1 * 32 + lane];
        uint4 p2 = Yq[(size_t)i2 * 32 + lane];
        uint4 p3 = Yq[(size_t)i3 * 32 + lane];
#pragma unroll
        for (int i = 0; i < 4; i++) {
            float2 f0 = __half22float2(((__half2*)&p0)[i]);
            float2 f1 = __half22float2(((__half2*)&p1)[i]);
            float2 f2 = __half22float2(((__half2*)&p2)[i]);
            float2 f3 = __half22float2(((__half2*)&p3)[i]);
            a[2 * i]     += (f0.x + f1.x) + (f2.x + f3.x);
            a[2 * i + 1] += (f0.y + f1.y) + (f2.y + f3.y);
        }
    }
    for (; e < e1; e++) {
        uint4 p = Yq[(size_t)g_src[e] * 32 + lane];
#pragma unroll
        for (int i = 0; i < 4; i++) {
            float2 f = __half22float2(((__half2*)&p)[i]);
            a[2 * i] += f.x; a[2 * i + 1] += f.y;
        }
    }

    float dv = g_dinv[c];
    float alpha = aptr[0];
    int colb = (lane & 15) * 8;
    float4 b0 = *(const float4*)(bias + colb);
    float4 b1 = *(const float4*)(bias + colb + 4);
    float4 o0, o1;
    o0.x = fmaf(dv, a[0], b0.x); o0.x = (o0.x >= 0.f) ? o0.x : alpha * o0.x;
    o0.y = fmaf(dv, a[1], b0.y); o0.y = (o0.y >= 0.f) ? o0.y : alpha * o0.y;
    o0.z = fmaf(dv, a[2], b0.z); o0.z = (o0.z >= 0.f) ? o0.z : alpha * o0.z;
    o0.w = fmaf(dv, a[3], b0.w); o0.w = (o0.w >= 0.f) ? o0.w : alpha * o0.w;
    o1.x = fmaf(dv, a[4], b1.x); o1.x = (o1.x >= 0.f) ? o1.x : alpha * o1.x;
    o1.y = fmaf(dv, a[5], b1.y); o1.y = (o1.y >= 0.f) ? o1.y : alpha * o1.y;
    o1.z = fmaf(dv, a[6], b1.z); o1.z = (o1.z >= 0.f) ? o1.z : alpha * o1.z;
    o1.w = fmaf(dv, a[7], b1.w); o1.w = (o1.w >= 0.f) ? o1.w : alpha * o1.w;

    size_t row = (size_t)(c + (lane >> 4) * NN) * D + colb;
    *(float4*)(g_H + row)     = o0;
    *(float4*)(g_H + row + 4) = o1;
}

// ---------------- readout ----------------
__global__ void colsum_kernel() {
    int col  = threadIdx.x & 127;
    int half = threadIdx.x >> 7;
    float s = 0.f;
    for (int r = blockIdx.x * 2 + half; r < NN; r += gridDim.x * 2)
        s += g_H[(size_t)r * D + col];
    __shared__ float sh[256];
    sh[threadIdx.x] = s;
    __syncthreads();
    if (half == 0) atomicAdd(&g_colsum[col], s + sh[threadIdx.x + 128]);
}

__global__ void wc_kernel(const float* __restrict__ Wb) {
    __shared__ float cs[128];
    int t = threadIdx.x;
    float m = g_colsum[t] / (float)NN;
    cs[t] = 1.f / (1.f + expf(-m));
    __syncthreads();
    float s = 0.f;
#pragma unroll 4
    for (int j = 0; j < 128; j++) s += Wb[(size_t)t * 128 + j] * cs[j];
    g_wc[t] = s;
}

// ---------------- scores ----------------
__global__ __launch_bounds__(256) void score_kernel(float* __restrict__ out,
                                                    const float* __restrict__ bb) {
    __shared__ float wcs[128];
    if (threadIdx.x < 128) wcs[threadIdx.x] = g_wc[threadIdx.x];
    __syncthreads();
    int warp = (blockIdx.x * blockDim.x + threadIdx.x) >> 5;
    int lane = threadIdx.x & 31;
    if (warp >= M2) return;
    const float4* H4 = (const float4*)g_H;
    float4 h = H4[(size_t)warp * 32 + lane];
    float w0 = wcs[lane * 4 + 0], w1 = wcs[lane * 4 + 1];
    float w2 = wcs[lane * 4 + 2], w3 = wcs[lane * 4 + 3];
    float s = h.x * w0 + h.y * w1 + h.z * w2 + h.w * w3;
#pragma unroll
    for (int o = 16; o > 0; o >>= 1) s += __shfl_xor_sync(0xffffffffu, s, o);
    if (lane == 0) out[warp] = s + bb[0];
}

// ---------------- launch ----------------
extern "C" void kernel_launch(void* const* d_in, const int* in_sizes, int n_in,
                              void* d_out, int out_size) {
    const float* seq1 = (const float*)d_in[0];
    const float* seq2 = (const float*)d_in[1];
    const void*  ei   = d_in[2];
    const float* W1   = (const float*)d_in[3];
    const float* b1   = (const float*)d_in[4];
    const float* W2   = (const float*)d_in[5];
    const float* b2   = (const float*)d_in[6];
    const float* W3   = (const float*)d_in[7];
    const float* b3   = (const float*)d_in[8];
    const float* ap   = (const float*)d_in[9];
    const float* Wb   = (const float*)d_in[10];
    const float* bb   = (const float*)d_in[11];

    init_kernel<<<(NN + 255) / 256, 256>>>((const int*)ei);
    hist_kernel<<<(EE / 4 + 255) / 256, 256>>>(ei);
    scan_kernel<<<1, 1024>>>();

    const int agg_blocks = (NN * 32 + 255) / 256;
    const int sc_blocks  = (M2 * 32 + 255) / 256;

    // fused: CSR-fill prologue + layer-1 GEMM
    gemm_fill_kernel<<<GEMM_BLOCKS, 256>>>(W1, seq1, seq2, ei);
    agg_kernel<<<agg_blocks, 256>>>(b1, ap);

    gemm_mma_kernel<<<GEMM_BLOCKS, 256>>>(W2);
    agg_kernel<<<agg_blocks, 256>>>(b2, ap);

    gemm_mma_kernel<<<GEMM_BLOCKS, 256>>>(W3);
    agg_kernel<<<agg_blocks, 256>>>(b3, ap);

    colsum_kernel<<<100, 256>>>();
    wc_kernel<<<1, 128>>>(Wb);

    score_kernel<<<sc_blocks, 256>>>((float*)d_out, bb);
}

// round 13
// speedup vs baseline: 1.1154x; 1.1154x over previous
#include <cuda_runtime.h>
#include <cuda_fp16.h>
#include <cstdint>

#define NN 10000
#define EE 640000
#define D  128
#define M2 (2*NN)
#define GEMM_BLOCKS (((M2 + 127) / 128) * 2)   // 314: (row-tile, N-half)
#define FILL_BLOCKS ((EE / 4 + 255) / 256)     // 625

// ---------------- scratch (static __device__, no allocation) ----------------
__device__ int   g_is64;
__device__ int   g_deg[NN];
__device__ int   g_rowptr[NN + 1];
__device__ float g_dinv[NN];
__device__ int   g_rank[EE];
__device__ int   g_src[EE];
__device__ __align__(16) float  g_H[(size_t)M2 * D];     // node features (both seqs)
__device__ __align__(16) __half g_Yh[(size_t)NN * 256];  // interleaved node row: 256 halves
__device__ __align__(16) __half g_Wh[3 * D * D];         // pre-split weights hi
__device__ __align__(16) __half g_Wl[3 * D * D];         // pre-split weights lo
__device__ float g_colsum[D];
__device__ float g_wc[D];

__device__ __forceinline__ unsigned h2_bits(__half2 h) {
    union { __half2 h; unsigned u; } cv; cv.h = h; return cv.u;
}
__device__ __forceinline__ uint32_t smem_u32(const void* p) {
    uint32_t a;
    asm("{ .reg .u64 t; cvta.to.shared.u64 t, %1; cvt.u32.u64 %0, t; }"
        : "=r"(a) : "l"(p));
    return a;
}

// ---------------- init + dtype probe (int64 => odd int32 words all zero) ----
__global__ void init_kernel(const int* __restrict__ ei32) {
    if (blockIdx.x == 0 && threadIdx.x < 32) {
        int odd = ei32[2 * threadIdx.x + 1];
        unsigned m = __ballot_sync(0xffffffffu, odd != 0);
        if (threadIdx.x == 0) g_is64 = (m == 0);
    }
    int i = blockIdx.x * blockDim.x + threadIdx.x;
    if (i < NN) g_deg[i] = 0;
    if (i < D)  g_colsum[i] = 0.f;
}

// ---------------- W pre-split: fp32 -> fp16 hi/lo, all 3 layers -------------
__global__ void wsplit_kernel(const float* __restrict__ W1,
                              const float* __restrict__ W2,
                              const float* __restrict__ W3) {
    int l = blockIdx.x >> 4;                       // 16 blocks per layer
    int idx4 = (blockIdx.x & 15) * 256 + threadIdx.x;  // 4096 float4 per layer
    const float* W = (l == 0) ? W1 : (l == 1) ? W2 : W3;
    float4 v = ((const float4*)W)[idx4];
    __half hx = __float2half_rn(v.x), hy = __float2half_rn(v.y);
    __half hz = __float2half_rn(v.z), hw = __float2half_rn(v.w);
    uint2 hi, lo;
    hi.x = h2_bits(__halves2half2(hx, hy));
    hi.y = h2_bits(__halves2half2(hz, hw));
    lo.x = h2_bits(__floats2half2_rn(v.x - __half2float(hx), v.y - __half2float(hy)));
    lo.y = h2_bits(__floats2half2_rn(v.z - __half2float(hz), v.w - __half2float(hw)));
    *(uint2*)(g_Wh + l * D * D + idx4 * 4) = hi;
    *(uint2*)(g_Wl + l * D * D + idx4 * 4) = lo;
}

// ---------------- histogram + per-edge rank: 4 edges/thread ----------------
__global__ void hist_kernel(const void* __restrict__ ei) {
    int e = (blockIdx.x * blockDim.x + threadIdx.x) * 4;
    if (e >= EE) return;
    int c0, c1, c2, c3;
    if (g_is64) {
        const ulonglong2* p = (const ulonglong2*)((const long long*)ei + EE + e);
        ulonglong2 v0 = p[0], v1 = p[1];
        c0 = (int)v0.x; c1 = (int)v0.y; c2 = (int)v1.x; c3 = (int)v1.y;
    } else {
        int4 v = *(const int4*)((const int*)ei + EE + e);
        c0 = v.x; c1 = v.y; c2 = v.z; c3 = v.w;
    }
    int4 rk;
    rk.x = ((unsigned)c0 < NN) ? atomicAdd(&g_deg[c0], 1) : -1;
    rk.y = ((unsigned)c1 < NN) ? atomicAdd(&g_deg[c1], 1) : -1;
    rk.z = ((unsigned)c2 < NN) ? atomicAdd(&g_deg[c2], 1) : -1;
    rk.w = ((unsigned)c3 < NN) ? atomicAdd(&g_deg[c3], 1) : -1;
    *(int4*)(g_rank + e) = rk;
}

// single block, 1024 threads, 10 elems/thread
__global__ void scan_kernel() {
    const int PER = 10;
    int tid  = threadIdx.x;
    int lane = tid & 31, w = tid >> 5;
    int base = tid * PER;
    int v[PER];
    int s = 0;
#pragma unroll
    for (int k = 0; k < PER; k++) {
        int i = base + k;
        int d = (i < NN) ? g_deg[i] : 0;
        v[k] = d; s += d;
        if (i < NN) g_dinv[i] = rsqrtf((float)(d + 1));
    }
    int ws = s;
#pragma unroll
    for (int o = 1; o < 32; o <<= 1) {
        int t = __shfl_up_sync(0xffffffffu, ws, o);
        if (lane >= o) ws += t;
    }
    __shared__ int wsum[32];
    if (lane == 31) wsum[w] = ws;
    __syncthreads();
    if (w == 0) {
        int x = wsum[lane];
#pragma unroll
        for (int o = 1; o < 32; o <<= 1) {
            int t = __shfl_up_sync(0xffffffffu, x, o);
            if (lane >= o) x += t;
        }
        wsum[lane] = x;
    }
    __syncthreads();
    int run = ws - s + (w ? wsum[w - 1] : 0);
#pragma unroll
    for (int k = 0; k < PER; k++) {
        int i = base + k;
        if (i <= NN) g_rowptr[i] = run;
        run += v[k];
    }
}

// ---------------- fill body (one virtual block of 256 threads, 4 edges/t) ---
__device__ __forceinline__ void fill_body(const void* __restrict__ ei, int vbid) {
    int e = (vbid * 256 + threadIdx.x) * 4;
    if (e >= EE) return;
    int r0, r1, r2, r3, c0, c1, c2, c3;
    if (g_is64) {
        const ulonglong2* pr = (const ulonglong2*)((const long long*)ei + e);
        const ulonglong2* pc = (const ulonglong2*)((const long long*)ei + EE + e);
        ulonglong2 a0 = pr[0], a1 = pr[1], b0 = pc[0], b1 = pc[1];
        r0 = (int)a0.x; r1 = (int)a0.y; r2 = (int)a1.x; r3 = (int)a1.y;
        c0 = (int)b0.x; c1 = (int)b0.y; c2 = (int)b1.x; c3 = (int)b1.y;
    } else {
        int4 a = *(const int4*)((const int*)ei + e);
        int4 b = *(const int4*)((const int*)ei + EE + e);
        r0 = a.x; r1 = a.y; r2 = a.z; r3 = a.w;
        c0 = b.x; c1 = b.y; c2 = b.z; c3 = b.w;
    }
    int4 rk = *(const int4*)(g_rank + e);
    if (rk.x >= 0 && (unsigned)r0 < NN) g_src[g_rowptr[c0] + rk.x] = r0;
    if (rk.y >= 0 && (unsigned)r1 < NN) g_src[g_rowptr[c1] + rk.y] = r1;
    if (rk.z >= 0 && (unsigned)r2 < NN) g_src[g_rowptr[c2] + rk.z] = r2;
    if (rk.w >= 0 && (unsigned)r3 < NN) g_src[g_rowptr[c3] + rk.w] = r3;
}

// ---------------- split-fp16 HMMA GEMM body: 128 rows x 64 cols per block ---
// Pre-split W in global; staging = plain fp16 copy. 8 warps x 16 rows.
#define WSTR2 72   // 64 cols + 8 pad halves (144B stride)

__device__ __forceinline__ void gemm_body(__half* Sh, __half* Sl, int layer,
                                          const float* __restrict__ base0,
                                          const float* __restrict__ base1,
                                          int bm, int nhalf) {
    int tid = threadIdx.x, wid = tid >> 5, lane = tid & 31;

    // stage 128x64 hi/lo fp16 tiles (copy from pre-split global)
    const __half* Gh = g_Wh + layer * D * D + nhalf * 64;
    const __half* Gl = g_Wl + layer * D * D + nhalf * 64;
    for (int idx = tid; idx < 128 * 8; idx += 256) {
        int row = idx >> 3, seg = (idx & 7) * 8;
        *(uint4*)(Sh + row * WSTR2 + seg) = *(const uint4*)(Gh + row * D + seg);
        *(uint4*)(Sl + row * WSTR2 + seg) = *(const uint4*)(Gl + row * D + seg);
    }

    int grpID = lane >> 2, tig = lane & 3;
    int m0 = bm + wid * 16 + grpID;
    int m1 = m0 + 8;
    int m0c = (m0 < M2) ? m0 : M2 - 1;
    int m1c = (m1 < M2) ? m1 : M2 - 1;
    const float* ap0 = (m0c < NN) ? (base0 + (size_t)m0c * D)
                                  : (base1 + (size_t)(m0c - NN) * D);
    const float* ap1 = (m1c < NN) ? (base0 + (size_t)m1c * D)
                                  : (base1 + (size_t)(m1c - NN) * D);

    float c[8][4];
#pragma unroll
    for (int t = 0; t < 8; t++)
#pragma unroll
        for (int j = 0; j < 4; j++) c[t][j] = 0.f;

    int krow = lane & 15;
    int ngrp = (lane >> 4) * 8;
    __syncthreads();

#pragma unroll
    for (int kt = 0; kt < 8; kt++) {
        int kc = kt * 16 + tig * 2;
        uint32_t ah[4], al[4];
#pragma unroll
        for (int q = 0; q < 4; q++) {
            const float* ap = (q & 1) ? ap1 : ap0;
            float2 v = *(const float2*)(ap + kc + (q >> 1) * 8);
            __half hx = __float2half_rn(v.x), hy = __float2half_rn(v.y);
            ah[q] = h2_bits(__halves2half2(hx, hy));
            al[q] = h2_bits(__floats2half2_rn(v.x - __half2float(hx),
                                              v.y - __half2float(hy)));
        }

        uint32_t rowoff = (uint32_t)(kt * 16 + krow) * (WSTR2 * 2) + ngrp * 2;
        uint32_t bh_addr = smem_u32(Sh) + rowoff;
        uint32_t bl_addr = smem_u32(Sl) + rowoff;
#pragma unroll
        for (int nt = 0; nt < 4; nt++) {
            uint32_t bh0, bh1, bh2, bh3, bl0, bl1, bl2, bl3;
            asm volatile(
                "ldmatrix.sync.aligned.m8n8.x4.trans.shared.b16 {%0,%1,%2,%3}, [%4];"
                : "=r"(bh0), "=r"(bh1), "=r"(bh2), "=r"(bh3)
                : "r"(bh_addr + nt * 32));
            asm volatile(
                "ldmatrix.sync.aligned.m8n8.x4.trans.shared.b16 {%0,%1,%2,%3}, [%4];"
                : "=r"(bl0), "=r"(bl1), "=r"(bl2), "=r"(bl3)
                : "r"(bl_addr + nt * 32));
#define MMA(CT, B0, B1, A0_, A1_, A2_, A3_)                                   \
    asm volatile(                                                             \
        "mma.sync.aligned.m16n8k16.row.col.f32.f16.f16.f32 "                  \
        "{%0,%1,%2,%3}, {%4,%5,%6,%7}, {%8,%9}, {%0,%1,%2,%3};"               \
        : "+f"(c[CT][0]), "+f"(c[CT][1]), "+f"(c[CT][2]), "+f"(c[CT][3])      \
        : "r"(A0_), "r"(A1_), "r"(A2_), "r"(A3_), "r"(B0), "r"(B1))
            MMA(nt * 2,     bh0, bh1, ah[0], ah[1], ah[2], ah[3]);
            MMA(nt * 2,     bh0, bh1, al[0], al[1], al[2], al[3]);
            MMA(nt * 2,     bl0, bl1, ah[0], ah[1], ah[2], ah[3]);
            MMA(nt * 2 + 1, bh2, bh3, ah[0], ah[1], ah[2], ah[3]);
            MMA(nt * 2 + 1, bh2, bh3, al[0], al[1], al[2], al[3]);
            MMA(nt * 2 + 1, bl2, bl3, ah[0], ah[1], ah[2], ah[3]);
#undef MMA
        }
    }

    // epilogue: scale by dinv, store fp16 into interleaved Y
    float dv0 = (m0 < M2) ? g_dinv[(m0 < NN) ? m0 : m0 - NN] : 0.f;
    float dv1 = (m1 < M2) ? g_dinv[(m1 < NN) ? m1 : m1 - NN] : 0.f;
    size_t y0 = (m0 < NN) ? ((size_t)m0 * 256) : ((size_t)(m0 - NN) * 256 + 128);
    size_t y1 = (m1 < NN) ? ((size_t)m1 * 256) : ((size_t)(m1 - NN) * 256 + 128);
#pragma unroll
    for (int t = 0; t < 8; t++) {
        int col = nhalf * 64 + t * 8 + tig * 2;
        if (m0 < M2)
            *(unsigned*)(g_Yh + y0 + col) =
                h2_bits(__floats2half2_rn(dv0 * c[t][0], dv0 * c[t][1]));
        if (m1 < M2)
            *(unsigned*)(g_Yh + y1 + col) =
                h2_bits(__floats2half2_rn(dv1 * c[t][2], dv1 * c[t][3]));
    }
}

// standalone GEMM (layers 2,3): grid 314
__global__ __launch_bounds__(256) void gemm_mma_kernel(int layer) {
    __shared__ __half Sh[128 * WSTR2];
    __shared__ __half Sl[128 * WSTR2];
    int bm = (blockIdx.x >> 1) * 128, nhalf = blockIdx.x & 1;
    gemm_body(Sh, Sl, layer, g_H, g_H + (size_t)NN * D, bm, nhalf);
}

// fused layer-1: GEMM blocks + CSR fill blocks side by side (R10 pattern)
__global__ __launch_bounds__(256) void gemm_fill_kernel(const float* __restrict__ seq1,
                                                        const float* __restrict__ seq2,
                                                        const void* __restrict__ ei) {
    __shared__ __half Sh[128 * WSTR2];
    __shared__ __half Sl[128 * WSTR2];
    if (blockIdx.x < GEMM_BLOCKS) {
        int bm = (blockIdx.x >> 1) * 128, nhalf = blockIdx.x & 1;
        gemm_body(Sh, Sl, 0, seq1, seq2, bm, nhalf);
    } else {
        fill_body(ei, blockIdx.x - GEMM_BLOCKS);
    }
}

// ------- aggregation: warp/node, 16B per lane per edge (both seqs fused) ----
__global__ __launch_bounds__(256) void agg_kernel(const float* __restrict__ bias,
                                                  const float* __restrict__ aptr) {
    int c    = (blockIdx.x * blockDim.x + threadIdx.x) >> 5;
    int lane = threadIdx.x & 31;
    if (c >= NN) return;

    const uint4* Yq = (const uint4*)g_Yh;   // 32 uint4 per node row (512B)
    float a[8];
    {
        uint4 p = Yq[(size_t)c * 32 + lane];     // self loop
        __half2* h = (__half2*)&p;
#pragma unroll
        for (int i = 0; i < 4; i++) {
            float2 f = __half22float2(h[i]);
            a[2 * i] = f.x; a[2 * i + 1] = f.y;
        }
    }

    int e = g_rowptr[c], e1 = g_rowptr[c + 1];
    for (; e + 4 <= e1; e += 4) {
        int i0 = g_src[e + 0], i1 = g_src[e + 1];
        int i2 = g_src[e + 2], i3 = g_src[e + 3];
        uint4 p0 = Yq[(size_t)i0 * 32 + lane];
        uint4 p1 = Yq[(size_t)i1 * 32 + lane];
        uint4 p2 = Yq[(size_t)i2 * 32 + lane];
        uint4 p3 = Yq[(size_t)i3 * 32 + lane];
#pragma unroll
        for (int i = 0; i < 4; i++) {
            float2 f0 = __half22float2(((__half2*)&p0)[i]);
            float2 f1 = __half22float2(((__half2*)&p1)[i]);
            float2 f2 = __half22float2(((__half2*)&p2)[i]);
            float2 f3 = __half22float2(((__half2*)&p3)[i]);
            a[2 * i]     += (f0.x + f1.x) + (f2.x + f3.x);
            a[2 * i + 1] += (f0.y + f1.y) + (f2.y + f3.y);
        }
    }
    for (; e < e1; e++) {
        uint4 p = Yq[(size_t)g_src[e] * 32 + lane];
#pragma unroll
        for (int i = 0; i < 4; i++) {
            float2 f = __half22float2(((__half2*)&p)[i]);
            a[2 * i] += f.x; a[2 * i + 1] += f.y;
        }
    }

    float dv = g_dinv[c];
    float alpha = aptr[0];
    int colb = (lane & 15) * 8;
    float4 b0 = *(const float4*)(bias + colb);
    float4 b1 = *(const float4*)(bias + colb + 4);
    float4 o0, o1;
    o0.x = fmaf(dv, a[0], b0.x); o0.x = (o0.x >= 0.f) ? o0.x : alpha * o0.x;
    o0.y = fmaf(dv, a[1], b0.y); o0.y = (o0.y >= 0.f) ? o0.y : alpha * o0.y;
    o0.z = fmaf(dv, a[2], b0.z); o0.z = (o0.z >= 0.f) ? o0.z : alpha * o0.z;
    o0.w = fmaf(dv, a[3], b0.w); o0.w = (o0.w >= 0.f) ? o0.w : alpha * o0.w;
    o1.x = fmaf(dv, a[4], b1.x); o1.x = (o1.x >= 0.f) ? o1.x : alpha * o1.x;
    o1.y = fmaf(dv, a[5], b1.y); o1.y = (o1.y >= 0.f) ? o1.y : alpha * o1.y;
    o1.z = fmaf(dv, a[6], b1.z); o1.z = (o1.z >= 0.f) ? o1.z : alpha * o1.z;
    o1.w = fmaf(dv, a[7], b1.w); o1.w = (o1.w >= 0.f) ? o1.w : alpha * o1.w;

    size_t row = (size_t)(c + (lane >> 4) * NN) * D + colb;
    *(float4*)(g_H + row)     = o0;
    *(float4*)(g_H + row + 4) = o1;
}

// ---------------- readout ----------------
__global__ void colsum_kernel() {
    int col  = threadIdx.x & 127;
    int half = threadIdx.x >> 7;
    float s = 0.f;
    for (int r = blockIdx.x * 2 + half; r < NN; r += gridDim.x * 2)
        s += g_H[(size_t)r * D + col];
    __shared__ float sh[256];
    sh[threadIdx.x] = s;
    __syncthreads();
    if (half == 0) atomicAdd(&g_colsum[col], s + sh[threadIdx.x + 128]);
}

__global__ void wc_kernel(const float* __restrict__ Wb) {
    __shared__ float cs[128];
    int t = threadIdx.x;
    float m = g_colsum[t] / (float)NN;
    cs[t] = 1.f / (1.f + expf(-m));
    __syncthreads();
    float s = 0.f;
#pragma unroll 4
    for (int j = 0; j < 128; j++) s += Wb[(size_t)t * 128 + j] * cs[j];
    g_wc[t] = s;
}

// ---------------- scores ----------------
__global__ __launch_bounds__(256) void score_kernel(float* __restrict__ out,
                                                    const float* __restrict__ bb) {
    __shared__ float wcs[128];
    if (threadIdx.x < 128) wcs[threadIdx.x] = g_wc[threadIdx.x];
    __syncthreads();
    int warp = (blockIdx.x * blockDim.x + threadIdx.x) >> 5;
    int lane = threadIdx.x & 31;
    if (warp >= M2) return;
    const float4* H4 = (const float4*)g_H;
    float4 h = H4[(size_t)warp * 32 + lane];
    float w0 = wcs[lane * 4 + 0], w1 = wcs[lane * 4 + 1];
    float w2 = wcs[lane * 4 + 2], w3 = wcs[lane * 4 + 3];
    float s = h.x * w0 + h.y * w1 + h.z * w2 + h.w * w3;
#pragma unroll
    for (int o = 16; o > 0; o >>= 1) s += __shfl_xor_sync(0xffffffffu, s, o);
    if (lane == 0) out[warp] = s + bb[0];
}

// ---------------- launch ----------------
extern "C" void kernel_launch(void* const* d_in, const int* in_sizes, int n_in,
                              void* d_out, int out_size) {
    const float* seq1 = (const float*)d_in[0];
    const float* seq2 = (const float*)d_in[1];
    const void*  ei   = d_in[2];
    const float* W1   = (const float*)d_in[3];
    const float* b1   = (const float*)d_in[4];
    const float* W2   = (const float*)d_in[5];
    const float* b2   = (const float*)d_in[6];
    const float* W3   = (const float*)d_in[7];
    const float* b3   = (const float*)d_in[8];
    const float* ap   = (const float*)d_in[9];
    const float* Wb   = (const float*)d_in[10];
    const float* bb   = (const float*)d_in[11];

    init_kernel<<<(NN + 255) / 256, 256>>>((const int*)ei);
    wsplit_kernel<<<48, 256>>>(W1, W2, W3);
    hist_kernel<<<(EE / 4 + 255) / 256, 256>>>(ei);
    scan_kernel<<<1, 1024>>>();

    const int agg_blocks = (NN * 32 + 255) / 256;
    const int sc_blocks  = (M2 * 32 + 255) / 256;

    // fused: layer-1 GEMM + CSR fill (side-by-side blocks)
    gemm_fill_kernel<<<GEMM_BLOCKS + FILL_BLOCKS, 256>>>(seq1, seq2, ei);
    agg_kernel<<<agg_blocks, 256>>>(b1, ap);

    gemm_mma_kernel<<<GEMM_BLOCKS, 256>>>(1);
    agg_kernel<<<agg_blocks, 256>>>(b2, ap);

    gemm_mma_kernel<<<GEMM_BLOCKS, 256>>>(2);
    agg_kernel<<<agg_blocks, 256>>>(b3, ap);

    colsum_kernel<<<100, 256>>>();
    wc_kernel<<<1, 128>>>(Wb);

    score_kernel<<<sc_blocks, 256>>>((float*)d_out, bb);
}

// round 15
// speedup vs baseline: 1.1698x; 1.0488x over previous
#include <cuda_runtime.h>
#include <cuda_fp16.h>
#include <cstdint>

#define NN 10000
#define EE 640000
#define D  128
#define M2 (2*NN)
#define GEMM_BLOCKS (((M2 + 127) / 128) * 2)   // 314: (row-tile, N-half)
#define FILL_BLOCKS ((EE / 4 + 255) / 256)     // 625
#define SCAN_BLOCKS ((NN + 255) / 256)         // 40

// ---------------- scratch (static __device__, no allocation) ----------------
__device__ int   g_is64;
__device__ int   g_deg[NN];
__device__ int   g_rowptr[NN + 1];
__device__ int   g_bsum[SCAN_BLOCKS];
__device__ float g_dinv[NN];
__device__ int   g_rank[EE];
__device__ int   g_src[EE];
__device__ __align__(16) float  g_H[(size_t)M2 * D];     // node features (both seqs)
__device__ __align__(16) __half g_Yh[(size_t)NN * 256];  // interleaved node row: 256 halves
__device__ __align__(16) __half g_Wh[3 * D * D];         // pre-split weights hi
__device__ __align__(16) __half g_Wl[3 * D * D];         // pre-split weights lo
__device__ float g_colsum[D];
__device__ float g_wc[D];

__device__ __forceinline__ unsigned h2_bits(__half2 h) {
    union { __half2 h; unsigned u; } cv; cv.h = h; return cv.u;
}
__device__ __forceinline__ uint32_t smem_u32(const void* p) {
    uint32_t a;
    asm("{ .reg .u64 t; cvta.to.shared.u64 t, %1; cvt.u32.u64 %0, t; }"
        : "=r"(a) : "l"(p));
    return a;
}

// ---------------- init + dtype probe (int64 => odd int32 words all zero) ----
__global__ void init_kernel(const int* __restrict__ ei32) {
    if (blockIdx.x == 0 && threadIdx.x < 32) {
        int odd = ei32[2 * threadIdx.x + 1];
        unsigned m = __ballot_sync(0xffffffffu, odd != 0);
        if (threadIdx.x == 0) g_is64 = (m == 0);
    }
    int i = blockIdx.x * blockDim.x + threadIdx.x;
    if (i < NN) g_deg[i] = 0;
    if (i < D)  g_colsum[i] = 0.f;
}

// ---------------- W pre-split: fp32 -> fp16 hi/lo, all 3 layers -------------
__global__ void wsplit_kernel(const float* __restrict__ W1,
                              const float* __restrict__ W2,
                              const float* __restrict__ W3) {
    int l = blockIdx.x >> 4;                       // 16 blocks per layer
    int idx4 = (blockIdx.x & 15) * 256 + threadIdx.x;  // 4096 float4 per layer
    const float* W = (l == 0) ? W1 : (l == 1) ? W2 : W3;
    float4 v = ((const float4*)W)[idx4];
    __half hx = __float2half_rn(v.x), hy = __float2half_rn(v.y);
    __half hz = __float2half_rn(v.z), hw = __float2half_rn(v.w);
    uint2 hi, lo;
    hi.x = h2_bits(__halves2half2(hx, hy));
    hi.y = h2_bits(__halves2half2(hz, hw));
    lo.x = h2_bits(__floats2half2_rn(v.x - __half2float(hx), v.y - __half2float(hy)));
    lo.y = h2_bits(__floats2half2_rn(v.z - __half2float(hz), v.w - __half2float(hw)));
    *(uint2*)(g_Wh + l * D * D + idx4 * 4) = hi;
    *(uint2*)(g_Wl + l * D * D + idx4 * 4) = lo;
}

// ---------------- histogram + per-edge rank: 4 edges/thread ----------------
__global__ void hist_kernel(const void* __restrict__ ei) {
    int e = (blockIdx.x * blockDim.x + threadIdx.x) * 4;
    if (e >= EE) return;
    int c0, c1, c2, c3;
    if (g_is64) {
        const ulonglong2* p = (const ulonglong2*)((const long long*)ei + EE + e);
        ulonglong2 v0 = p[0], v1 = p[1];
        c0 = (int)v0.x; c1 = (int)v0.y; c2 = (int)v1.x; c3 = (int)v1.y;
    } else {
        int4 v = *(const int4*)((const int*)ei + EE + e);
        c0 = v.x; c1 = v.y; c2 = v.z; c3 = v.w;
    }
    int4 rk;
    rk.x = ((unsigned)c0 < NN) ? atomicAdd(&g_deg[c0], 1) : -1;
    rk.y = ((unsigned)c1 < NN) ? atomicAdd(&g_deg[c1], 1) : -1;
    rk.z = ((unsigned)c2 < NN) ? atomicAdd(&g_deg[c2], 1) : -1;
    rk.w = ((unsigned)c3 < NN) ? atomicAdd(&g_deg[c3], 1) : -1;
    *(int4*)(g_rank + e) = rk;
}

// ---------------- scan stage 1: per-block exclusive scan + block sums -------
__global__ void scan1_kernel() {
    int tid = threadIdx.x, bid = blockIdx.x;
    int i = bid * 256 + tid;
    int d = (i < NN) ? g_deg[i] : 0;
    if (i < NN) g_dinv[i] = rsqrtf((float)(d + 1));  // +1 self loop
    int lane = tid & 31, w = tid >> 5;
    int ws = d;
#pragma unroll
    for (int o = 1; o < 32; o <<= 1) {
        int t = __shfl_up_sync(0xffffffffu, ws, o);
        if (lane >= o) ws += t;
    }
    __shared__ int wsum[8];
    if (lane == 31) wsum[w] = ws;
    __syncthreads();
    if (tid < 8) {
        int x = wsum[tid];
#pragma unroll
        for (int o = 1; o < 8; o <<= 1) {
            int t = __shfl_up_sync(0xffu, x, o, 8);
            if ((tid & 7) >= o) x += t;
        }
        wsum[tid] = x;
    }
    __syncthreads();
    int excl = ws - d + (w ? wsum[w - 1] : 0);
    if (i < NN) g_rowptr[i] = excl;          // partial (no global offset yet)
    if (tid == 255) g_bsum[bid] = excl + d;  // block total
}

// ---------------- scan stage 2: add block offsets ---------------------------
__global__ void scan2_kernel() {
    __shared__ int sb[SCAN_BLOCKS];
    __shared__ int boff_s;
    int tid = threadIdx.x, bid = blockIdx.x;
    if (tid < SCAN_BLOCKS) sb[tid] = g_bsum[tid];
    __syncthreads();
    if (tid == 0) {
        int s = 0;
        for (int j = 0; j < bid; j++) s += sb[j];
        boff_s = s;
    }
    __syncthreads();
    int i = bid * 256 + tid;
    if (i < NN) g_rowptr[i] += boff_s;
    if (bid == SCAN_BLOCKS - 1 && tid == 0) {
        int t = 0;
        for (int j = 0; j < SCAN_BLOCKS; j++) t += sb[j];
        g_rowptr[NN] = t;
    }
}

// ---------------- fill body (one virtual block of 256 threads, 4 edges/t) ---
__device__ __forceinline__ void fill_body(const void* __restrict__ ei, int vbid) {
    int e = (vbid * 256 + threadIdx.x) * 4;
    if (e >= EE) return;
    int r0, r1, r2, r3, c0, c1, c2, c3;
    if (g_is64) {
        const ulonglong2* pr = (const ulonglong2*)((const long long*)ei + e);
        const ulonglong2* pc = (const ulonglong2*)((const long long*)ei + EE + e);
        ulonglong2 a0 = pr[0], a1 = pr[1], b0 = pc[0], b1 = pc[1];
        r0 = (int)a0.x; r1 = (int)a0.y; r2 = (int)a1.x; r3 = (int)a1.y;
        c0 = (int)b0.x; c1 = (int)b0.y; c2 = (int)b1.x; c3 = (int)b1.y;
    } else {
        int4 a = *(const int4*)((const int*)ei + e);
        int4 b = *(const int4*)((const int*)ei + EE + e);
        r0 = a.x; r1 = a.y; r2 = a.z; r3 = a.w;
        c0 = b.x; c1 = b.y; c2 = b.z; c3 = b.w;
    }
    int4 rk = *(const int4*)(g_rank + e);
    if (rk.x >= 0 && (unsigned)r0 < NN) g_src[g_rowptr[c0] + rk.x] = r0;
    if (rk.y >= 0 && (unsigned)r1 < NN) g_src[g_rowptr[c1] + rk.y] = r1;
    if (rk.z >= 0 && (unsigned)r2 < NN) g_src[g_rowptr[c2] + rk.z] = r2;
    if (rk.w >= 0 && (unsigned)r3 < NN) g_src[g_rowptr[c3] + rk.w] = r3;
}

// ---------------- split-fp16 HMMA GEMM body: 128 rows x 64 cols per block ---
#define WSTR2 72   // 64 cols + 8 pad halves (144B stride)

__device__ __forceinline__ void gemm_body(__half* Sh, __half* Sl, int layer,
                                          const float* __restrict__ base0,
                                          const float* __restrict__ base1,
                                          int bm, int nhalf) {
    int tid = threadIdx.x, wid = tid >> 5, lane = tid & 31;

    // stage 128x64 hi/lo fp16 tiles (copy from pre-split global)
    const __half* Gh = g_Wh + layer * D * D + nhalf * 64;
    const __half* Gl = g_Wl + layer * D * D + nhalf * 64;
    for (int idx = tid; idx < 128 * 8; idx += 256) {
        int row = idx >> 3, seg = (idx & 7) * 8;
        *(uint4*)(Sh + row * WSTR2 + seg) = *(const uint4*)(Gh + row * D + seg);
        *(uint4*)(Sl + row * WSTR2 + seg) = *(const uint4*)(Gl + row * D + seg);
    }

    int grpID = lane >> 2, tig = lane & 3;
    int m0 = bm + wid * 16 + grpID;
    int m1 = m0 + 8;
    int m0c = (m0 < M2) ? m0 : M2 - 1;
    int m1c = (m1 < M2) ? m1 : M2 - 1;
    const float* ap0 = (m0c < NN) ? (base0 + (size_t)m0c * D)
                                  : (base1 + (size_t)(m0c - NN) * D);
    const float* ap1 = (m1c < NN) ? (base0 + (size_t)m1c * D)
                                  : (base1 + (size_t)(m1c - NN) * D);

    float c[8][4];
#pragma unroll
    for (int t = 0; t < 8; t++)
#pragma unroll
        for (int j = 0; j < 4; j++) c[t][j] = 0.f;

    int krow = lane & 15;
    int ngrp = (lane >> 4) * 8;
    __syncthreads();

#pragma unroll
    for (int kt = 0; kt < 8; kt++) {
        int kc = kt * 16 + tig * 2;
        uint32_t ah[4], al[4];
#pragma unroll
        for (int q = 0; q < 4; q++) {
            const float* ap = (q & 1) ? ap1 : ap0;
            float2 v = *(const float2*)(ap + kc + (q >> 1) * 8);
            __half hx = __float2half_rn(v.x), hy = __float2half_rn(v.y);
            ah[q] = h2_bits(__halves2half2(hx, hy));
            al[q] = h2_bits(__floats2half2_rn(v.x - __half2float(hx),
                                              v.y - __half2float(hy)));
        }

        uint32_t rowoff = (uint32_t)(kt * 16 + krow) * (WSTR2 * 2) + ngrp * 2;
        uint32_t bh_addr = smem_u32(Sh) + rowoff;
        uint32_t bl_addr = smem_u32(Sl) + rowoff;
#pragma unroll
        for (int nt = 0; nt < 4; nt++) {
            uint32_t bh0, bh1, bh2, bh3, bl0, bl1, bl2, bl3;
            asm volatile(
                "ldmatrix.sync.aligned.m8n8.x4.trans.shared.b16 {%0,%1,%2,%3}, [%4];"
                : "=r"(bh0), "=r"(bh1), "=r"(bh2), "=r"(bh3)
                : "r"(bh_addr + nt * 32));
            asm volatile(
                "ldmatrix.sync.aligned.m8n8.x4.trans.shared.b16 {%0,%1,%2,%3}, [%4];"
                : "=r"(bl0), "=r"(bl1), "=r"(bl2), "=r"(bl3)
                : "r"(bl_addr + nt * 32));
#define MMA(CT, B0, B1, A0_, A1_, A2_, A3_)                                   \
    asm volatile(                                                             \
        "mma.sync.aligned.m16n8k16.row.col.f32.f16.f16.f32 "                  \
        "{%0,%1,%2,%3}, {%4,%5,%6,%7}, {%8,%9}, {%0,%1,%2,%3};"               \
        : "+f"(c[CT][0]), "+f"(c[CT][1]), "+f"(c[CT][2]), "+f"(c[CT][3])      \
        : "r"(A0_), "r"(A1_), "r"(A2_), "r"(A3_), "r"(B0), "r"(B1))
            MMA(nt * 2,     bh0, bh1, ah[0], ah[1], ah[2], ah[3]);
            MMA(nt * 2,     bh0, bh1, al[0], al[1], al[2], al[3]);
            MMA(nt * 2,     bl0, bl1, ah[0], ah[1], ah[2], ah[3]);
            MMA(nt * 2 + 1, bh2, bh3, ah[0], ah[1], ah[2], ah[3]);
            MMA(nt * 2 + 1, bh2, bh3, al[0], al[1], al[2], al[3]);
            MMA(nt * 2 + 1, bl2, bl3, ah[0], ah[1], ah[2], ah[3]);
#undef MMA
        }
    }

    // epilogue: scale by dinv, store fp16 into interleaved Y
    float dv0 = (m0 < M2) ? g_dinv[(m0 < NN) ? m0 : m0 - NN] : 0.f;
    float dv1 = (m1 < M2) ? g_dinv[(m1 < NN) ? m1 : m1 - NN] : 0.f;
    size_t y0 = (m0 < NN) ? ((size_t)m0 * 256) : ((size_t)(m0 - NN) * 256 + 128);
    size_t y1 = (m1 < NN) ? ((size_t)m1 * 256) : ((size_t)(m1 - NN) * 256 + 128);
#pragma unroll
    for (int t = 0; t < 8; t++) {
        int col = nhalf * 64 + t * 8 + tig * 2;
        if (m0 < M2)
            *(unsigned*)(g_Yh + y0 + col) =
                h2_bits(__floats2half2_rn(dv0 * c[t][0], dv0 * c[t][1]));
        if (m1 < M2)
            *(unsigned*)(g_Yh + y1 + col) =
                h2_bits(__floats2half2_rn(dv1 * c[t][2], dv1 * c[t][3]));
    }
}

// standalone GEMM (layers 2,3): grid 314
__global__ __launch_bounds__(256) void gemm_mma_kernel(int layer) {
    __shared__ __half Sh[128 * WSTR2];
    __shared__ __half Sl[128 * WSTR2];
    int bm = (blockIdx.x >> 1) * 128, nhalf = blockIdx.x & 1;
    gemm_body(Sh, Sl, layer, g_H, g_H + (size_t)NN * D, bm, nhalf);
}

// fused layer-1: GEMM blocks + CSR fill blocks side by side
__global__ __launch_bounds__(256) void gemm_fill_kernel(const float* __restrict__ seq1,
                                                        const float* __restrict__ seq2,
                                                        const void* __restrict__ ei) {
    __shared__ __half Sh[128 * WSTR2];
    __shared__ __half Sl[128 * WSTR2];
    if (blockIdx.x < GEMM_BLOCKS) {
        int bm = (blockIdx.x >> 1) * 128, nhalf = blockIdx.x & 1;
        gemm_body(Sh, Sl, 0, seq1, seq2, bm, nhalf);
    } else {
        fill_body(ei, blockIdx.x - GEMM_BLOCKS);
    }
}

// ------- aggregation: warp/node, 16B per lane per edge (both seqs fused) ----
__global__ __launch_bounds__(256) void agg_kernel(const float* __restrict__ bias,
                                                  const float* __restrict__ aptr) {
    int c    = (blockIdx.x * blockDim.x + threadIdx.x) >> 5;
    int lane = threadIdx.x & 31;
    if (c >= NN) return;

    const uint4* Yq = (const uint4*)g_Yh;   // 32 uint4 per node row (512B)
    float a[8];
    {
        uint4 p = Yq[(size_t)c * 32 + lane];     // self loop
        __half2* h = (__half2*)&p;
#pragma unroll
        for (int i = 0; i < 4; i++) {
            float2 f = __half22float2(h[i]);
            a[2 * i] = f.x; a[2 * i + 1] = f.y;
        }
    }

    int e = g_rowptr[c], e1 = g_rowptr[c + 1];
    for (; e + 4 <= e1; e += 4) {
        int i0 = g_src[e + 0], i1 = g_src[e + 1];
        int i2 = g_src[e + 2], i3 = g_src[e + 3];
        uint4 p0 = Yq[(size_t)i0 * 32 + lane];
        uint4 p1 = Yq[(size_t)i1 * 32 + lane];
        uint4 p2 = Yq[(size_t)i2 * 32 + lane];
        uint4 p3 = Yq[(size_t)i3 * 32 + lane];
#pragma unroll
        for (int i = 0; i < 4; i++) {
            float2 f0 = __half22float2(((__half2*)&p0)[i]);
            float2 f1 = __half22float2(((__half2*)&p1)[i]);
            float2 f2 = __half22float2(((__half2*)&p2)[i]);
            float2 f3 = __half22float2(((__half2*)&p3)[i]);
            a[2 * i]     += (f0.x + f1.x) + (f2.x + f3.x);
            a[2 * i + 1] += (f0.y + f1.y) + (f2.y + f3.y);
        }
    }
    for (; e < e1; e++) {
        uint4 p = Yq[(size_t)g_src[e] * 32 + lane];
#pragma unroll
        for (int i = 0; i < 4; i++) {
            float2 f = __half22float2(((__half2*)&p)[i]);
            a[2 * i] += f.x; a[2 * i + 1] += f.y;
        }
    }

    float dv = g_dinv[c];
    float alpha = aptr[0];
    int colb = (lane & 15) * 8;
    float4 b0 = *(const float4*)(bias + colb);
    float4 b1 = *(const float4*)(bias + colb + 4);
    float4 o0, o1;
    o0.x = fmaf(dv, a[0], b0.x); o0.x = (o0.x >= 0.f) ? o0.x : alpha * o0.x;
    o0.y = fmaf(dv, a[1], b0.y); o0.y = (o0.y >= 0.f) ? o0.y : alpha * o0.y;
    o0.z = fmaf(dv, a[2], b0.z); o0.z = (o0.z >= 0.f) ? o0.z : alpha * o0.z;
    o0.w = fmaf(dv, a[3], b0.w); o0.w = (o0.w >= 0.f) ? o0.w : alpha * o0.w;
    o1.x = fmaf(dv, a[4], b1.x); o1.x = (o1.x >= 0.f) ? o1.x : alpha * o1.x;
    o1.y = fmaf(dv, a[5], b1.y); o1.y = (o1.y >= 0.f) ? o1.y : alpha * o1.y;
    o1.z = fmaf(dv, a[6], b1.z); o1.z = (o1.z >= 0.f) ? o1.z : alpha * o1.z;
    o1.w = fmaf(dv, a[7], b1.w); o1.w = (o1.w >= 0.f) ? o1.w : alpha * o1.w;

    size_t row = (size_t)(c + (lane >> 4) * NN) * D + colb;
    *(float4*)(g_H + row)     = o0;
    *(float4*)(g_H + row + 4) = o1;
}

// ---------------- readout ----------------
__global__ void colsum_kernel() {
    int col  = threadIdx.x & 127;
    int half = threadIdx.x >> 7;
    float s = 0.f;
    for (int r = blockIdx.x * 2 + half; r < NN; r += gridDim.x * 2)
        s += g_H[(size_t)r * D + col];
    __shared__ float sh[256];
    sh[threadIdx.x] = s;
    __syncthreads();
    if (half == 0) atomicAdd(&g_colsum[col], s + sh[threadIdx.x + 128]);
}

__global__ void wc_kernel(const float* __restrict__ Wb) {
    __shared__ float cs[128];
    int t = threadIdx.x;
    float m = g_colsum[t] / (float)NN;
    cs[t] = 1.f / (1.f + expf(-m));
    __syncthreads();
    float s = 0.f;
#pragma unroll 4
    for (int j = 0; j < 128; j++) s += Wb[(size_t)t * 128 + j] * cs[j];
    g_wc[t] = s;
}

// ---------------- scores ----------------
__global__ __launch_bounds__(256) void score_kernel(float* __restrict__ out,
                                                    const float* __restrict__ bb) {
    __shared__ float wcs[128];
    if (threadIdx.x < 128) wcs[threadIdx.x] = g_wc[threadIdx.x];
    __syncthreads();
    int warp = (blockIdx.x * blockDim.x + threadIdx.x) >> 5;
    int lane = threadIdx.x & 31;
    if (warp >= M2) return;
    const float4* H4 = (const float4*)g_H;
    float4 h = H4[(size_t)warp * 32 + lane];
    float w0 = wcs[lane * 4 + 0], w1 = wcs[lane * 4 + 1];
    float w2 = wcs[lane * 4 + 2], w3 = wcs[lane * 4 + 3];
    float s = h.x * w0 + h.y * w1 + h.z * w2 + h.w * w3;
#pragma unroll
    for (int o = 16; o > 0; o >>= 1) s += __shfl_xor_sync(0xffffffffu, s, o);
    if (lane == 0) out[warp] = s + bb[0];
}

// ---------------- launch ----------------
extern "C" void kernel_launch(void* const* d_in, const int* in_sizes, int n_in,
                              void* d_out, int out_size) {
    const float* seq1 = (const float*)d_in[0];
    const float* seq2 = (const float*)d_in[1];
    const void*  ei   = d_in[2];
    const float* W1   = (const float*)d_in[3];
    const float* b1   = (const float*)d_in[4];
    const float* W2   = (const float*)d_in[5];
    const float* b2   = (const float*)d_in[6];
    const float* W3   = (const float*)d_in[7];
    const float* b3   = (const float*)d_in[8];
    const float* ap   = (const float*)d_in[9];
    const float* Wb   = (const float*)d_in[10];
    const float* bb   = (const float*)d_in[11];

    init_kernel<<<(NN + 255) / 256, 256>>>((const int*)ei);
    wsplit_kernel<<<48, 256>>>(W1, W2, W3);
    hist_kernel<<<(EE / 4 + 255) / 256, 256>>>(ei);
    scan1_kernel<<<SCAN_BLOCKS, 256>>>();
    scan2_kernel<<<SCAN_BLOCKS, 256>>>();

    const int agg_blocks = (NN * 32 + 255) / 256;
    const int sc_blocks  = (M2 * 32 + 255) / 256;

    // fused: layer-1 GEMM + CSR fill (side-by-side blocks)
    gemm_fill_kernel<<<GEMM_BLOCKS + FILL_BLOCKS, 256>>>(seq1, seq2, ei);
    agg_kernel<<<agg_blocks, 256>>>(b1, ap);

    gemm_mma_kernel<<<GEMM_BLOCKS, 256>>>(1);
    agg_kernel<<<agg_blocks, 256>>>(b2, ap);

    gemm_mma_kernel<<<GEMM_BLOCKS, 256>>>(2);
    agg_kernel<<<agg_blocks, 256>>>(b3, ap);

    colsum_kernel<<<100, 256>>>();
    wc_kernel<<<1, 128>>>(Wb);

    score_kernel<<<sc_blocks, 256>>>((float*)d_out, bb);
}